// round 16
// baseline (speedup 1.0000x reference)
#include <cuda_runtime.h>
#include <cuda_bf16.h>
#include <math.h>
#include <stdint.h>

// ---------------------------------------------------------------------------
// Problem constants
// ---------------------------------------------------------------------------
#define Bb   2
#define Lseq 2048
#define Emb  1024
#define NH   16
#define DHd  64
#define FFd  4096
#define ROWS (Bb * Lseq)   // 4096
#define QKVS (3 * Emb)     // fused qkv row stride
// reference MULTIPLIES scores by sqrt(dh) = 8; we fold log2(e) into it for exp2:
#define SCALE_LOG2E 11.541560327111707f   // 8 * log2(e)

// ---------------------------------------------------------------------------
// Scratch (no allocations allowed: __device__ globals)
// ---------------------------------------------------------------------------
__device__ __nv_bfloat16 g_xn_h [ROWS * Emb];
__device__ __nv_bfloat16 g_xn_l [ROWS * Emb];
__device__ __nv_bfloat16 g_hn_h [ROWS * Emb];
__device__ __nv_bfloat16 g_hn_l [ROWS * Emb];
__device__ __nv_bfloat16 g_ctx_h[ROWS * Emb];
__device__ __nv_bfloat16 g_ctx_l[ROWS * Emb];
__device__ __nv_bfloat16 g_up_h [ROWS * FFd];
__device__ __nv_bfloat16 g_up_l [ROWS * FFd];
__device__ __nv_bfloat16 g_qkv_h[ROWS * QKVS], g_qkv_l[ROWS * QKVS];
__device__ float g_hidden[ROWS * Emb];
// split weights, ORIGINAL [K, N] layout, bf16 h/l
__device__ __nv_bfloat16 g_wq_h[Emb * Emb], g_wq_l[Emb * Emb];
__device__ __nv_bfloat16 g_wk_h[Emb * Emb], g_wk_l[Emb * Emb];
__device__ __nv_bfloat16 g_wv_h[Emb * Emb], g_wv_l[Emb * Emb];
__device__ __nv_bfloat16 g_wo_h[Emb * Emb], g_wo_l[Emb * Emb];
__device__ __nv_bfloat16 g_wu_h[Emb * FFd], g_wu_l[Emb * FFd];
__device__ __nv_bfloat16 g_wd_h[FFd * Emb], g_wd_l[FFd * Emb];

// ---------------------------------------------------------------------------
// Helpers
// ---------------------------------------------------------------------------
__device__ __forceinline__ uint32_t cvta_s(const void* p) {
    return (uint32_t)__cvta_generic_to_shared(p);
}

__device__ __forceinline__ float ex2(float x) {
    float y;
    asm("ex2.approx.ftz.f32 %0, %1;" : "=f"(y) : "f"(x));
    return y;
}

__device__ __forceinline__ void splitpack(float a, float b, uint32_t& h, uint32_t& l) {
    __nv_bfloat16 ha = __float2bfloat16(a), hb = __float2bfloat16(b);
    __nv_bfloat16 la = __float2bfloat16(a - __bfloat162float(ha));
    __nv_bfloat16 lb = __float2bfloat16(b - __bfloat162float(hb));
    h = ((uint32_t)__bfloat16_as_ushort(hb) << 16) | (uint32_t)__bfloat16_as_ushort(ha);
    l = ((uint32_t)__bfloat16_as_ushort(lb) << 16) | (uint32_t)__bfloat16_as_ushort(la);
}

__device__ __forceinline__ void split_store4(float4 v, __nv_bfloat16* h, __nv_bfloat16* l) {
    uint32_t h01, l01, h23, l23;
    splitpack(v.x, v.y, h01, l01);
    splitpack(v.z, v.w, h23, l23);
    ((uint32_t*)h)[0] = h01; ((uint32_t*)h)[1] = h23;
    ((uint32_t*)l)[0] = l01; ((uint32_t*)l)[1] = l23;
}

__device__ __forceinline__ void ldsm_x4(uint32_t r[4], uint32_t a) {
    asm volatile("ldmatrix.sync.aligned.m8n8.x4.shared.b16 {%0,%1,%2,%3}, [%4];"
                 : "=r"(r[0]), "=r"(r[1]), "=r"(r[2]), "=r"(r[3]) : "r"(a));
}
__device__ __forceinline__ void ldsm_x4t(uint32_t r[4], uint32_t a) {
    asm volatile("ldmatrix.sync.aligned.m8n8.x4.trans.shared.b16 {%0,%1,%2,%3}, [%4];"
                 : "=r"(r[0]), "=r"(r[1]), "=r"(r[2]), "=r"(r[3]) : "r"(a));
}
__device__ __forceinline__ void mma_bf16(float c[4], const uint32_t a[4], const uint32_t b[2]) {
    asm volatile("mma.sync.aligned.m16n8k16.row.col.f32.bf16.bf16.f32 "
                 "{%0,%1,%2,%3}, {%4,%5,%6,%7}, {%8,%9}, {%0,%1,%2,%3};"
                 : "+f"(c[0]), "+f"(c[1]), "+f"(c[2]), "+f"(c[3])
                 : "r"(a[0]), "r"(a[1]), "r"(a[2]), "r"(a[3]), "r"(b[0]), "r"(b[1]));
}

__device__ __forceinline__ float gelu_exact(float v) {
    return 0.5f * v * (1.0f + erff(v * 0.70710678118654752440f));
}

// cp.async (compiles on this toolchain; tcgen05 does NOT)
__device__ __forceinline__ void cp16(uint32_t dst, const void* src) {
    asm volatile("cp.async.cg.shared.global [%0], [%1], 16;" :: "r"(dst), "l"(src));
}
__device__ __forceinline__ void cp_commit() { asm volatile("cp.async.commit_group;"); }
__device__ __forceinline__ void cp_wait0()  { asm volatile("cp.async.wait_group 0;" ::: "memory"); }

// ---------------------------------------------------------------------------
// Merged weight split: all 6 weights in one launch (pointer-select by block).
// ---------------------------------------------------------------------------
__global__ void __launch_bounds__(256)
split6_kernel(const float* w0, __nv_bfloat16* h0, __nv_bfloat16* l0,
              const float* w1, __nv_bfloat16* h1, __nv_bfloat16* l1,
              const float* w2, __nv_bfloat16* h2, __nv_bfloat16* l2,
              const float* w3, __nv_bfloat16* h3, __nv_bfloat16* l3,
              const float* w4, __nv_bfloat16* h4, __nv_bfloat16* l4,
              const float* w5, __nv_bfloat16* h5, __nv_bfloat16* l5)
{
    const int b = blockIdx.x;
    const float* W; __nv_bfloat16 *H, *L; size_t off;
    if      (b < 1024) { W = w0; H = h0; L = l0; off = (size_t)b * 1024; }
    else if (b < 2048) { W = w1; H = h1; L = l1; off = (size_t)(b - 1024) * 1024; }
    else if (b < 3072) { W = w2; H = h2; L = l2; off = (size_t)(b - 2048) * 1024; }
    else if (b < 4096) { W = w3; H = h3; L = l3; off = (size_t)(b - 3072) * 1024; }
    else if (b < 8192) { W = w4; H = h4; L = l4; off = (size_t)(b - 4096) * 1024; }
    else               { W = w5; H = h5; L = l5; off = (size_t)(b - 8192) * 1024; }
    const size_t i = off + threadIdx.x * 4;
    float4 v = *(const float4*)(W + i);
    split_store4(v, H + i, L + i);
}

// ---------------------------------------------------------------------------
// LayerNorm: writes split bf16 (h, l)
// ---------------------------------------------------------------------------
__global__ void __launch_bounds__(256)
layernorm_kernel(const float* __restrict__ x, const float* __restrict__ w,
                 const float* __restrict__ bsh,
                 __nv_bfloat16* __restrict__ yh, __nv_bfloat16* __restrict__ yl)
{
    __shared__ float s1[256];
    __shared__ float s2[256];
    const int tid = threadIdx.x;
    const size_t row = blockIdx.x;
    const float4* xr = (const float4*)(x + row * Emb);
    float4 v = xr[tid];

    float a = v.x + v.y + v.z + v.w;
    float b = v.x * v.x + v.y * v.y + v.z * v.z + v.w * v.w;
    s1[tid] = a; s2[tid] = b;
    __syncthreads();
    #pragma unroll
    for (int st = 128; st > 0; st >>= 1) {
        if (tid < st) { s1[tid] += s1[tid + st]; s2[tid] += s2[tid + st]; }
        __syncthreads();
    }
    const float mu   = s1[0] * (1.0f / Emb);
    const float var  = s2[0] * (1.0f / Emb) - mu * mu;
    const float rstd = rsqrtf(var + 1e-5f);

    float4 wv = ((const float4*)w)[tid];
    float4 bv = ((const float4*)bsh)[tid];
    float4 o;
    o.x = (v.x - mu) * rstd * wv.x + bv.x;
    o.y = (v.y - mu) * rstd * wv.y + bv.y;
    o.z = (v.z - mu) * rstd * wv.z + bv.z;
    o.w = (v.w - mu) * rstd * wv.w + bv.w;
    split_store4(o, yh + row * Emb + tid * 4, yl + row * Emb + tid * 4);
}

// ---------------------------------------------------------------------------
// GEMM tiling constants (75776 B smem; launch_bounds targets 2 CTAs/SM)
// ---------------------------------------------------------------------------
#define BM 128
#define BN 128
#define BK 32
#define PA 40
#define PB 136
#define AT_ELE (BM * PA)                       // 5120 bf16 per A tile
#define BT_ELE (BK * PB)                       // 4352 bf16 per B tile
#define BUF_ELE (2 * AT_ELE + 2 * BT_ELE)      // 18944 bf16 per buffer
#define GEMM_SMEM (2 * BUF_ELE * 2)            // 75776 bytes

__device__ __forceinline__ void stage_tile(
    __nv_bfloat16* buf,
    const __nv_bfloat16* __restrict__ Ah_g, const __nv_bfloat16* __restrict__ Al_g,
    const __nv_bfloat16* __restrict__ Bh_g, const __nv_bfloat16* __restrict__ Bl_g,
    int bm, int bn, int k0, int N, int K, int tid)
{
    __nv_bfloat16* Ah = buf;
    __nv_bfloat16* Al = buf + AT_ELE;
    __nv_bfloat16* Bh = buf + 2 * AT_ELE;
    __nv_bfloat16* Bl = buf + 2 * AT_ELE + BT_ELE;
    #pragma unroll
    for (int i = 0; i < 2; i++) {
        const int u   = tid + 256 * i;
        const int row = u >> 2;
        const int kc  = (u & 3) * 8;
        const size_t go = (size_t)(bm + row) * K + k0 + kc;
        cp16(cvta_s(Ah + row * PA + kc), Ah_g + go);
        cp16(cvta_s(Al + row * PA + kc), Al_g + go);
    }
    #pragma unroll
    for (int i = 0; i < 2; i++) {
        const int u   = tid + 256 * i;
        const int row = u >> 4;
        const int nc  = (u & 15) * 8;
        const size_t go = (size_t)(k0 + row) * N + bn + nc;
        cp16(cvta_s(Bh + row * PB + nc), Bh_g + go);
        cp16(cvta_s(Bl + row * PB + nc), Bl_g + go);
    }
}

// Inner compute for one staged buffer (shared by both GEMM kernels).
__device__ __forceinline__ void gemm_tile_compute(
    const __nv_bfloat16* buf, float acc[4][4][4],
    int wm, int wn, int a_r, int a_kh, int b_c4)
{
    const __nv_bfloat16* Ahb = buf;
    const __nv_bfloat16* Alb = buf + AT_ELE;
    const __nv_bfloat16* Bhb = buf + 2 * AT_ELE;
    const __nv_bfloat16* Blb = buf + 2 * AT_ELE + BT_ELE;

    #pragma unroll
    for (int kk = 0; kk < BK; kk += 16) {
        uint32_t ah[4][4], al[4][4];
        #pragma unroll
        for (int mi = 0; mi < 4; mi++) {
            const int row = wm + mi * 16 + a_r;
            const int kc  = kk + a_kh;
            ldsm_x4(ah[mi], cvta_s(Ahb + row * PA + kc));
            ldsm_x4(al[mi], cvta_s(Alb + row * PA + kc));
        }
        #pragma unroll
        for (int ni2 = 0; ni2 < 2; ni2++) {
            const int n0 = wn + ni2 * 16;
            uint32_t bh4[4], bl4[4];
            const int boff = (kk + a_r) * PB + n0 + b_c4;
            ldsm_x4t(bh4, cvta_s(Bhb + boff));
            ldsm_x4t(bl4, cvta_s(Blb + boff));
            #pragma unroll
            for (int mi = 0; mi < 4; mi++) {
                mma_bf16(acc[mi][2 * ni2],     ah[mi], &bh4[0]);
                mma_bf16(acc[mi][2 * ni2],     al[mi], &bh4[0]);
                mma_bf16(acc[mi][2 * ni2],     ah[mi], &bl4[0]);
                mma_bf16(acc[mi][2 * ni2 + 1], ah[mi], &bh4[2]);
                mma_bf16(acc[mi][2 * ni2 + 1], al[mi], &bh4[2]);
                mma_bf16(acc[mi][2 * ni2 + 1], ah[mi], &bl4[2]);
            }
        }
    }
}

// ---------------------------------------------------------------------------
// Generic bf16-split GEMM, PERSISTENT tiles (1D grid, stride over tiles).
// EPI: 1 = bias+res fp32 out; 2 = bias+GELU split out.
// Safety of cross-tile smem reuse: nk is even (K/32 ∈ {32,128}), so the last
// compute of a tile reads buf1 while the next tile's prologue stages buf0;
// per-iteration __syncthreads bounds warp skew to < 1 k-tile.
// ---------------------------------------------------------------------------
template <int EPI>
__global__ void __launch_bounds__(256, 2)
mma_gemm_kernel(const __nv_bfloat16* __restrict__ Ah_g, const __nv_bfloat16* __restrict__ Al_g,
                const __nv_bfloat16* __restrict__ Bh_g, const __nv_bfloat16* __restrict__ Bl_g,
                const float* __restrict__ bias, const float* __restrict__ res,
                float* __restrict__ Cf,
                __nv_bfloat16* __restrict__ Ch, __nv_bfloat16* __restrict__ Cl,
                int nx, int ntiles, int N, int K)
{
    extern __shared__ __nv_bfloat16 smb[];

    const int tid  = threadIdx.x;
    const int lane = tid & 31;
    const int warp = tid >> 5;
    const int wm   = (warp >> 2) * 64;
    const int wn   = (warp & 3) * 32;
    const int g    = lane >> 2;
    const int tg   = lane & 3;

    const int a_r  = (lane & 7) + ((lane >> 3) & 1) * 8;
    const int a_kh = (lane >> 4) * 8;
    const int b_c4 = (lane >> 4) * 8;
    const int nk   = K >> 5;

    for (int tile = blockIdx.x; tile < ntiles; tile += gridDim.x) {
        const int bm = (tile / nx) * BM;
        const int bn = (tile % nx) * BN;

        float acc[4][4][4];
        #pragma unroll
        for (int mi = 0; mi < 4; mi++)
            #pragma unroll
            for (int ni = 0; ni < 4; ni++)
                #pragma unroll
                for (int c = 0; c < 4; c++) acc[mi][ni][c] = 0.0f;

        stage_tile(smb, Ah_g, Al_g, Bh_g, Bl_g, bm, bn, 0, N, K, tid);
        cp_commit();

        for (int t = 0; t < nk; t++) {
            cp_wait0();
            __syncthreads();
            if (t + 1 < nk) {
                stage_tile(smb + ((t + 1) & 1) * BUF_ELE, Ah_g, Al_g, Bh_g, Bl_g,
                           bm, bn, (t + 1) << 5, N, K, tid);
                cp_commit();
            }
            gemm_tile_compute(smb + (t & 1) * BUF_ELE, acc, wm, wn, a_r, a_kh, b_c4);
        }

        #pragma unroll
        for (int mi = 0; mi < 4; mi++) {
            #pragma unroll
            for (int ni = 0; ni < 4; ni++) {
                const int col = bn + wn + ni * 8 + tg * 2;
                const float bx = bias[col], by = bias[col + 1];
                #pragma unroll
                for (int half = 0; half < 2; half++) {
                    const size_t row = (size_t)(bm + wm + mi * 16 + g + half * 8);
                    float vx = acc[mi][ni][half * 2 + 0] + bx;
                    float vy = acc[mi][ni][half * 2 + 1] + by;
                    if (EPI == 1) {
                        float2 rv = *(const float2*)&res[row * N + col];
                        vx += rv.x; vy += rv.y;
                    }
                    if (EPI == 2) {
                        vx = gelu_exact(vx); vy = gelu_exact(vy);
                        uint32_t h, l;
                        splitpack(vx, vy, h, l);
                        *(uint32_t*)&Ch[row * N + col] = h;
                        *(uint32_t*)&Cl[row * N + col] = l;
                    } else {
                        *(float2*)&Cf[row * N + col] = make_float2(vx, vy);
                    }
                }
            }
        }
    }
}

// ---------------------------------------------------------------------------
// Fused QKV GEMM, PERSISTENT tiles: 768 tiles (24 x 32); slab-selects wq/wk/wv.
// Output: interleaved [ROWS, 3072] split bf16.
// ---------------------------------------------------------------------------
__global__ void __launch_bounds__(256, 2)
qkv_gemm_kernel(const __nv_bfloat16* __restrict__ Ah_g, const __nv_bfloat16* __restrict__ Al_g,
                const __nv_bfloat16* __restrict__ w0h, const __nv_bfloat16* __restrict__ w0l,
                const __nv_bfloat16* __restrict__ w1h, const __nv_bfloat16* __restrict__ w1l,
                const __nv_bfloat16* __restrict__ w2h, const __nv_bfloat16* __restrict__ w2l,
                const float* __restrict__ b0, const float* __restrict__ b1,
                const float* __restrict__ b2,
                __nv_bfloat16* __restrict__ Ch, __nv_bfloat16* __restrict__ Cl)
{
    extern __shared__ __nv_bfloat16 smb[];

    const int tid  = threadIdx.x;
    const int lane = tid & 31;
    const int warp = tid >> 5;
    const int wm   = (warp >> 2) * 64;
    const int wn   = (warp & 3) * 32;
    const int g    = lane >> 2;
    const int tg   = lane & 3;

    const int a_r  = (lane & 7) + ((lane >> 3) & 1) * 8;
    const int a_kh = (lane >> 4) * 8;
    const int b_c4 = (lane >> 4) * 8;
    const int nk   = Emb >> 5;   // 32

    for (int tile = blockIdx.x; tile < 24 * 32; tile += gridDim.x) {
        const int bx = tile % 24;
        const int bm = (tile / 24) * BM;
        const int which = bx >> 3;
        const __nv_bfloat16* Bh_g = (which == 0) ? w0h : (which == 1) ? w1h : w2h;
        const __nv_bfloat16* Bl_g = (which == 0) ? w0l : (which == 1) ? w1l : w2l;
        const float* bias         = (which == 0) ? b0  : (which == 1) ? b1  : b2;
        const int bnL = (bx & 7) * BN;   // within this weight's N=1024
        const int bnO = bx * BN;         // within 3072 output

        float acc[4][4][4];
        #pragma unroll
        for (int mi = 0; mi < 4; mi++)
            #pragma unroll
            for (int ni = 0; ni < 4; ni++)
                #pragma unroll
                for (int c = 0; c < 4; c++) acc[mi][ni][c] = 0.0f;

        stage_tile(smb, Ah_g, Al_g, Bh_g, Bl_g, bm, bnL, 0, Emb, Emb, tid);
        cp_commit();

        for (int t = 0; t < nk; t++) {
            cp_wait0();
            __syncthreads();
            if (t + 1 < nk) {
                stage_tile(smb + ((t + 1) & 1) * BUF_ELE, Ah_g, Al_g, Bh_g, Bl_g,
                           bm, bnL, (t + 1) << 5, Emb, Emb, tid);
                cp_commit();
            }
            gemm_tile_compute(smb + (t & 1) * BUF_ELE, acc, wm, wn, a_r, a_kh, b_c4);
        }

        // epilogue: bias + splitpack into [ROWS, 3072]
        #pragma unroll
        for (int mi = 0; mi < 4; mi++) {
            #pragma unroll
            for (int ni = 0; ni < 4; ni++) {
                const int colL = bnL + wn + ni * 8 + tg * 2;
                const int colO = bnO + wn + ni * 8 + tg * 2;
                const float bx2 = bias[colL], by2 = bias[colL + 1];
                #pragma unroll
                for (int half = 0; half < 2; half++) {
                    const size_t row = (size_t)(bm + wm + mi * 16 + g + half * 8);
                    float vx = acc[mi][ni][half * 2 + 0] + bx2;
                    float vy = acc[mi][ni][half * 2 + 1] + by2;
                    uint32_t h, l;
                    splitpack(vx, vy, h, l);
                    *(uint32_t*)&Ch[row * QKVS + colO] = h;
                    *(uint32_t*)&Cl[row * QKVS + colO] = l;
                }
            }
        }
    }
}

// ---------------------------------------------------------------------------
// Tensor-core flash attention over the fused qkv buffer.
// Q staged into buffer 0, fragments hoisted, buffer 0 recycled for KV.
// Single sync per K-tile. exp2-domain softmax (scale = 8*log2e, exact math).
// ---------------------------------------------------------------------------
#define PQ 72
#define KV_ELE   (64 * PQ)             // 4608 ele per array
#define KVBUF_ELE (4 * KV_ELE)         // 18432 ele per buffer (36864 B)
#define ATTN_SMEM (2 * KVBUF_ELE * 2)  // 73728 bytes

__device__ __forceinline__ void stage_kv(
    __nv_bfloat16* buf,
    const __nv_bfloat16* __restrict__ qkvh, const __nv_bfloat16* __restrict__ qkvl,
    size_t kbase, size_t vbase, int c0, int tid)
{
    #pragma unroll
    for (int i = 0; i < 2; i++) {
        const int u = tid + 256 * i;
        const int r = u >> 3;
        const int c = (u & 7) * 8;
        const size_t gk = kbase + (size_t)(c0 + r) * QKVS + c;
        const size_t gv = vbase + (size_t)(c0 + r) * QKVS + c;
        const int so = r * PQ + c;
        cp16(cvta_s(buf + 0 * KV_ELE + so), qkvh + gk);
        cp16(cvta_s(buf + 1 * KV_ELE + so), qkvl + gk);
        cp16(cvta_s(buf + 2 * KV_ELE + so), qkvh + gv);
        cp16(cvta_s(buf + 3 * KV_ELE + so), qkvl + gv);
    }
}

__global__ void __launch_bounds__(256, 2)
flash_attn_kernel(const __nv_bfloat16* __restrict__ qkvh, const __nv_bfloat16* __restrict__ qkvl,
                  __nv_bfloat16* __restrict__ Oh, __nv_bfloat16* __restrict__ Ol)
{
    extern __shared__ __nv_bfloat16 sb[];   // [2][KVBUF_ELE]

    const int tid  = threadIdx.x;
    const int lane = tid & 31;
    const int warp = tid >> 5;
    const int g    = lane >> 2;
    const int tg   = lane & 3;
    const int l7   = lane & 7;
    const int b8   = (lane >> 3) & 1;
    const int b16  = lane >> 4;

    const int bh = blockIdx.y;
    const int b = bh >> 4, h = bh & 15;
    const int q0 = blockIdx.x << 7;
    const size_t bb    = (size_t)b * Lseq * QKVS;
    const size_t qbase = bb + (size_t)h * DHd;
    const size_t kbase = qbase + Emb;
    const size_t vbase = qbase + 2 * Emb;

    // ---- stage Q into buffer 0 ----
    {
        __nv_bfloat16* Qh = sb;
        __nv_bfloat16* Ql = sb + 128 * PQ;
        #pragma unroll
        for (int i = 0; i < 4; i++) {
            const int u = tid + 256 * i;
            const int r = u >> 3;
            const int c = (u & 7) * 8;
            const size_t go = qbase + (size_t)(q0 + r) * QKVS + c;
            cp16(cvta_s(Qh + r * PQ + c), qkvh + go);
            cp16(cvta_s(Ql + r * PQ + c), qkvl + go);
        }
    }
    cp_commit();
    cp_wait0();
    __syncthreads();

    // ---- Q fragments -> registers ----
    const int a_r  = l7 + b8 * 8;
    const int a_kh = b16 * 8;
    uint32_t qfh[4][4], qfl[4][4];
    {
        const __nv_bfloat16* Qh = sb;
        const __nv_bfloat16* Ql = sb + 128 * PQ;
        const int row = warp * 16 + a_r;
        #pragma unroll
        for (int ks = 0; ks < 4; ks++) {
            const int kc = 16 * ks + a_kh;
            ldsm_x4(qfh[ks], cvta_s(Qh + row * PQ + kc));
            ldsm_x4(qfl[ks], cvta_s(Ql + row * PQ + kc));
        }
    }
    __syncthreads();   // buffer 0 is now free

    // ---- KV tile 0 -> buffer 1 ----
    stage_kv(sb + KVBUF_ELE, qkvh, qkvl, kbase, vbase, 0, tid);
    cp_commit();

    float oacc[8][4];
    #pragma unroll
    for (int nj = 0; nj < 8; nj++)
        #pragma unroll
        for (int c = 0; c < 4; c++) oacc[nj][c] = 0.0f;
    float mA = -1e30f, mB = -1e30f, lA = 0.0f, lB = 0.0f;

    const int nkb = Lseq / 64;
    for (int kb = 0; kb < nkb; kb++) {
        cp_wait0();
        __syncthreads();
        if (kb + 1 < nkb) {
            stage_kv(sb + (kb & 1) * KVBUF_ELE, qkvh, qkvl, kbase, vbase,
                     (kb + 1) << 6, tid);
            cp_commit();
        }

        const __nv_bfloat16* cur = sb + ((kb + 1) & 1) * KVBUF_ELE;
        const __nv_bfloat16* Kh = cur;
        const __nv_bfloat16* Kl = cur + KV_ELE;
        const __nv_bfloat16* Vh = cur + 2 * KV_ELE;
        const __nv_bfloat16* Vl = cur + 3 * KV_ELE;

        // ---- S = Q K^T (K b-frags via non-trans x4: two n-groups per ld) ----
        float sacc[8][4];
        #pragma unroll
        for (int ni = 0; ni < 8; ni++)
            #pragma unroll
            for (int c = 0; c < 4; c++) sacc[ni][c] = 0.0f;

        #pragma unroll
        for (int ks = 0; ks < 4; ks++) {
            #pragma unroll
            for (int ni2 = 0; ni2 < 4; ni2++) {
                const int n0 = ni2 * 16;
                uint32_t kh4[4], kl4[4];
                const int koff = (n0 + l7 + b16 * 8) * PQ + 16 * ks + b8 * 8;
                ldsm_x4(kh4, cvta_s(Kh + koff));
                ldsm_x4(kl4, cvta_s(Kl + koff));
                mma_bf16(sacc[2 * ni2],     qfh[ks], &kh4[0]);
                mma_bf16(sacc[2 * ni2],     qfl[ks], &kh4[0]);
                mma_bf16(sacc[2 * ni2],     qfh[ks], &kl4[0]);
                mma_bf16(sacc[2 * ni2 + 1], qfh[ks], &kh4[2]);
                mma_bf16(sacc[2 * ni2 + 1], qfl[ks], &kh4[2]);
                mma_bf16(sacc[2 * ni2 + 1], qfh[ks], &kl4[2]);
            }
        }
        // scale into exp2 domain: t = (8*log2e) * (q.k)  ->  e^(8 q.k) = 2^t
        #pragma unroll
        for (int ni = 0; ni < 8; ni++) {
            sacc[ni][0] *= SCALE_LOG2E; sacc[ni][1] *= SCALE_LOG2E;
            sacc[ni][2] *= SCALE_LOG2E; sacc[ni][3] *= SCALE_LOG2E;
        }

        // ---- online softmax in exp2 domain (rows g and g+8) ----
        float tA = -1e30f, tB = -1e30f;
        #pragma unroll
        for (int ni = 0; ni < 8; ni++) {
            tA = fmaxf(tA, fmaxf(sacc[ni][0], sacc[ni][1]));
            tB = fmaxf(tB, fmaxf(sacc[ni][2], sacc[ni][3]));
        }
        tA = fmaxf(tA, __shfl_xor_sync(0xffffffffu, tA, 1));
        tA = fmaxf(tA, __shfl_xor_sync(0xffffffffu, tA, 2));
        tB = fmaxf(tB, __shfl_xor_sync(0xffffffffu, tB, 1));
        tB = fmaxf(tB, __shfl_xor_sync(0xffffffffu, tB, 2));

        const float mAn = fmaxf(mA, tA), mBn = fmaxf(mB, tB);
        const float aA = ex2(mA - mAn), aB = ex2(mB - mBn);
        mA = mAn; mB = mBn;

        float sA = 0.0f, sB = 0.0f;
        #pragma unroll
        for (int ni = 0; ni < 8; ni++) {
            float p0 = ex2(sacc[ni][0] - mAn);
            float p1 = ex2(sacc[ni][1] - mAn);
            float p2 = ex2(sacc[ni][2] - mBn);
            float p3 = ex2(sacc[ni][3] - mBn);
            sacc[ni][0] = p0; sacc[ni][1] = p1;
            sacc[ni][2] = p2; sacc[ni][3] = p3;
            sA += p0 + p1; sB += p2 + p3;
        }
        sA += __shfl_xor_sync(0xffffffffu, sA, 1);
        sA += __shfl_xor_sync(0xffffffffu, sA, 2);
        sB += __shfl_xor_sync(0xffffffffu, sB, 1);
        sB += __shfl_xor_sync(0xffffffffu, sB, 2);
        lA = lA * aA + sA;
        lB = lB * aB + sB;

        #pragma unroll
        for (int nj = 0; nj < 8; nj++) {
            oacc[nj][0] *= aA; oacc[nj][1] *= aA;
            oacc[nj][2] *= aB; oacc[nj][3] *= aB;
        }

        // ---- O += P V (V b-frags via x4t: two n-groups per ld) ----
        #pragma unroll
        for (int ks = 0; ks < 4; ks++) {
            uint32_t pfh[4], pfl[4];
            splitpack(sacc[2 * ks][0],     sacc[2 * ks][1],     pfh[0], pfl[0]);
            splitpack(sacc[2 * ks][2],     sacc[2 * ks][3],     pfh[1], pfl[1]);
            splitpack(sacc[2 * ks + 1][0], sacc[2 * ks + 1][1], pfh[2], pfl[2]);
            splitpack(sacc[2 * ks + 1][2], sacc[2 * ks + 1][3], pfh[3], pfl[3]);
            #pragma unroll
            for (int nj2 = 0; nj2 < 4; nj2++) {
                const int n0 = nj2 * 16;
                uint32_t vh4[4], vl4[4];
                const int voff = (16 * ks + a_r) * PQ + n0 + b16 * 8;
                ldsm_x4t(vh4, cvta_s(Vh + voff));
                ldsm_x4t(vl4, cvta_s(Vl + voff));
                mma_bf16(oacc[2 * nj2],     pfh, &vh4[0]);
                mma_bf16(oacc[2 * nj2],     pfl, &vh4[0]);
                mma_bf16(oacc[2 * nj2],     pfh, &vl4[0]);
                mma_bf16(oacc[2 * nj2 + 1], pfh, &vh4[2]);
                mma_bf16(oacc[2 * nj2 + 1], pfl, &vh4[2]);
                mma_bf16(oacc[2 * nj2 + 1], pfh, &vl4[2]);
            }
        }
    }

    // ---- finalize: ctx = O / l, written as split bf16 (stride Emb) ----
    const float iA = 1.0f / lA, iB = 1.0f / lB;
    const size_t obase = (size_t)b * Lseq * Emb + (size_t)h * DHd;
    const int rowA = q0 + warp * 16 + g;
    #pragma unroll
    for (int nj = 0; nj < 8; nj++) {
        const int d = nj * 8 + tg * 2;
        uint32_t hA, lAa, hB, lBb;
        splitpack(oacc[nj][0] * iA, oacc[nj][1] * iA, hA, lAa);
        splitpack(oacc[nj][2] * iB, oacc[nj][3] * iB, hB, lBb);
        const size_t offA = obase + (size_t)rowA * Emb + d;
        const size_t offB = obase + (size_t)(rowA + 8) * Emb + d;
        *(uint32_t*)&Oh[offA] = hA;  *(uint32_t*)&Ol[offA] = lAa;
        *(uint32_t*)&Oh[offB] = hB;  *(uint32_t*)&Ol[offB] = lBb;
    }
}

// ---------------------------------------------------------------------------
// Launch
// ---------------------------------------------------------------------------
extern "C" void kernel_launch(void* const* d_in, const int* in_sizes, int n_in,
                              void* d_out, int out_size)
{
    const float* x     = (const float*)d_in[0];
    const float* ln1_w = (const float*)d_in[1];
    const float* ln1_b = (const float*)d_in[2];
    const float* wq    = (const float*)d_in[3];
    const float* bq    = (const float*)d_in[4];
    const float* wk    = (const float*)d_in[5];
    const float* bk    = (const float*)d_in[6];
    const float* wv    = (const float*)d_in[7];
    const float* bv    = (const float*)d_in[8];
    const float* wo    = (const float*)d_in[9];
    const float* bo    = (const float*)d_in[10];
    const float* ln2_w = (const float*)d_in[11];
    const float* ln2_b = (const float*)d_in[12];
    const float* wu    = (const float*)d_in[13];
    const float* bu    = (const float*)d_in[14];
    const float* wd    = (const float*)d_in[15];
    const float* bd    = (const float*)d_in[16];
    float* out = (float*)d_out;

    __nv_bfloat16 *xnh, *xnl, *hnh, *hnl, *ctxh, *ctxl, *uph, *upl, *qkvh, *qkvl;
    __nv_bfloat16 *wqh, *wql, *wkh, *wkl, *wvh, *wvl, *woh, *wol, *wuh, *wul, *wdh, *wdl;
    float *hidden;
    cudaGetSymbolAddress((void**)&xnh,  g_xn_h);  cudaGetSymbolAddress((void**)&xnl,  g_xn_l);
    cudaGetSymbolAddress((void**)&hnh,  g_hn_h);  cudaGetSymbolAddress((void**)&hnl,  g_hn_l);
    cudaGetSymbolAddress((void**)&ctxh, g_ctx_h); cudaGetSymbolAddress((void**)&ctxl, g_ctx_l);
    cudaGetSymbolAddress((void**)&uph,  g_up_h);  cudaGetSymbolAddress((void**)&upl,  g_up_l);
    cudaGetSymbolAddress((void**)&qkvh, g_qkv_h); cudaGetSymbolAddress((void**)&qkvl, g_qkv_l);
    cudaGetSymbolAddress((void**)&hidden, g_hidden);
    cudaGetSymbolAddress((void**)&wqh, g_wq_h);   cudaGetSymbolAddress((void**)&wql, g_wq_l);
    cudaGetSymbolAddress((void**)&wkh, g_wk_h);   cudaGetSymbolAddress((void**)&wkl, g_wk_l);
    cudaGetSymbolAddress((void**)&wvh, g_wv_h);   cudaGetSymbolAddress((void**)&wvl, g_wv_l);
    cudaGetSymbolAddress((void**)&woh, g_wo_h);   cudaGetSymbolAddress((void**)&wol, g_wo_l);
    cudaGetSymbolAddress((void**)&wuh, g_wu_h);   cudaGetSymbolAddress((void**)&wul, g_wu_l);
    cudaGetSymbolAddress((void**)&wdh, g_wd_h);   cudaGetSymbolAddress((void**)&wdl, g_wd_l);

    cudaFuncSetAttribute(mma_gemm_kernel<1>, cudaFuncAttributeMaxDynamicSharedMemorySize, GEMM_SMEM);
    cudaFuncSetAttribute(mma_gemm_kernel<2>, cudaFuncAttributeMaxDynamicSharedMemorySize, GEMM_SMEM);
    cudaFuncSetAttribute(qkv_gemm_kernel,    cudaFuncAttributeMaxDynamicSharedMemorySize, GEMM_SMEM);
    cudaFuncSetAttribute(flash_attn_kernel,  cudaFuncAttributeMaxDynamicSharedMemorySize, ATTN_SMEM);

    // persistent-grid slot count: 2 CTAs per SM
    int smCount = 148;
    cudaDeviceGetAttribute(&smCount, cudaDevAttrMultiProcessorCount, 0);
    const int nslots = 2 * smCount;
    const int gQKV = (768  < nslots) ? 768  : nslots;
    const int gUP  = (1024 < nslots) ? 1024 : nslots;
    const int gE   = (256  < nslots) ? 256  : nslots;

    // 0) split all weights in one launch
    split6_kernel<<<12288, 256>>>(wq, wqh, wql, wk, wkh, wkl, wv, wvh, wvl,
                                  wo, woh, wol, wu, wuh, wul, wd, wdh, wdl);

    // 1) LN1 -> split xn
    layernorm_kernel<<<ROWS, 256>>>(x, ln1_w, ln1_b, xnh, xnl);
    // 2) fused QKV projection -> split [ROWS, 3072] (persistent, 768 tiles)
    qkv_gemm_kernel<<<gQKV, 256, GEMM_SMEM>>>(xnh, xnl,
                                              wqh, wql, wkh, wkl, wvh, wvl,
                                              bq, bk, bv, qkvh, qkvl);
    // 3) Flash attention -> split ctx
    flash_attn_kernel<<<dim3(Lseq / 128, Bb * NH), 256, ATTN_SMEM>>>(qkvh, qkvl, ctxh, ctxl);
    // 4) O projection + residual -> hidden (fp32)  [256 tiles]
    mma_gemm_kernel<1><<<gE, 256, GEMM_SMEM>>>(ctxh, ctxl, woh, wol, bo, x, hidden,
                                               nullptr, nullptr, 8, 256, Emb, Emb);
    // 5) LN2 -> split hn
    layernorm_kernel<<<ROWS, 256>>>(hidden, ln2_w, ln2_b, hnh, hnl);
    // 6) FFN up + GELU -> split up  [1024 tiles, persistent]
    mma_gemm_kernel<2><<<gUP, 256, GEMM_SMEM>>>(hnh, hnl, wuh, wul, bu, nullptr, nullptr,
                                                uph, upl, 32, 1024, FFd, Emb);
    // 7) FFN down + bias + residual -> out (fp32)  [256 tiles]
    mma_gemm_kernel<1><<<gE, 256, GEMM_SMEM>>>(uph, upl, wdh, wdl, bd, hidden, out,
                                               nullptr, nullptr, 8, 256, Emb, FFd);
}

// round 17
// speedup vs baseline: 1.0106x; 1.0106x over previous
#include <cuda_runtime.h>
#include <cuda_bf16.h>
#include <math.h>
#include <stdint.h>

// ---------------------------------------------------------------------------
// Problem constants
// ---------------------------------------------------------------------------
#define Bb   2
#define Lseq 2048
#define Emb  1024
#define NH   16
#define DHd  64
#define FFd  4096
#define ROWS (Bb * Lseq)   // 4096
#define QKVS (3 * Emb)     // fused qkv row stride
// reference MULTIPLIES scores by sqrt(dh) = 8; fold log2(e) for exp2 domain:
#define SCALE_LOG2E 11.541560327111707f   // 8 * log2(e)

// ---------------------------------------------------------------------------
// Scratch (no allocations allowed: __device__ globals)
// ---------------------------------------------------------------------------
__device__ __nv_bfloat16 g_xn_h [ROWS * Emb];
__device__ __nv_bfloat16 g_xn_l [ROWS * Emb];
__device__ __nv_bfloat16 g_hn_h [ROWS * Emb];
__device__ __nv_bfloat16 g_hn_l [ROWS * Emb];
__device__ __nv_bfloat16 g_ctx_h[ROWS * Emb];
__device__ __nv_bfloat16 g_ctx_l[ROWS * Emb];
__device__ __nv_bfloat16 g_up_h [ROWS * FFd];
__device__ __nv_bfloat16 g_up_l [ROWS * FFd];
__device__ __nv_bfloat16 g_qkv_h[ROWS * QKVS], g_qkv_l[ROWS * QKVS];
__device__ float g_hidden[ROWS * Emb];
// split weights, ORIGINAL [K, N] layout, bf16 h/l
__device__ __nv_bfloat16 g_wq_h[Emb * Emb], g_wq_l[Emb * Emb];
__device__ __nv_bfloat16 g_wk_h[Emb * Emb], g_wk_l[Emb * Emb];
__device__ __nv_bfloat16 g_wv_h[Emb * Emb], g_wv_l[Emb * Emb];
__device__ __nv_bfloat16 g_wo_h[Emb * Emb], g_wo_l[Emb * Emb];
__device__ __nv_bfloat16 g_wu_h[Emb * FFd], g_wu_l[Emb * FFd];
__device__ __nv_bfloat16 g_wd_h[FFd * Emb], g_wd_l[FFd * Emb];

// ---------------------------------------------------------------------------
// Helpers
// ---------------------------------------------------------------------------
__device__ __forceinline__ uint32_t cvta_s(const void* p) {
    return (uint32_t)__cvta_generic_to_shared(p);
}

__device__ __forceinline__ float ex2(float x) {
    float y;
    asm("ex2.approx.ftz.f32 %0, %1;" : "=f"(y) : "f"(x));
    return y;
}

// Fast 2-value split: h = pack(bf16(a), bf16(b)) in ONE cvt; residuals via
// shift-based bf16->f32 (exact) and exact fp32 subtract; pack l in ONE cvt.
// Bit-identical to the scalar __float2bfloat16 path (same rn rounding).
__device__ __forceinline__ void splitpack(float a, float b, uint32_t& h, uint32_t& l) {
    uint32_t hp;
    asm("cvt.rn.bf16x2.f32 %0, %1, %2;" : "=r"(hp) : "f"(b), "f"(a));
    const float ha = __uint_as_float(hp << 16);
    const float hb = __uint_as_float(hp & 0xFFFF0000u);
    const float la = a - ha;
    const float lb = b - hb;
    asm("cvt.rn.bf16x2.f32 %0, %1, %2;" : "=r"(l) : "f"(lb), "f"(la));
    h = hp;
}

__device__ __forceinline__ void split_store4(float4 v, __nv_bfloat16* h, __nv_bfloat16* l) {
    uint32_t h01, l01, h23, l23;
    splitpack(v.x, v.y, h01, l01);
    splitpack(v.z, v.w, h23, l23);
    ((uint32_t*)h)[0] = h01; ((uint32_t*)h)[1] = h23;
    ((uint32_t*)l)[0] = l01; ((uint32_t*)l)[1] = l23;
}

__device__ __forceinline__ void ldsm_x4(uint32_t r[4], uint32_t a) {
    asm volatile("ldmatrix.sync.aligned.m8n8.x4.shared.b16 {%0,%1,%2,%3}, [%4];"
                 : "=r"(r[0]), "=r"(r[1]), "=r"(r[2]), "=r"(r[3]) : "r"(a));
}
__device__ __forceinline__ void ldsm_x4t(uint32_t r[4], uint32_t a) {
    asm volatile("ldmatrix.sync.aligned.m8n8.x4.trans.shared.b16 {%0,%1,%2,%3}, [%4];"
                 : "=r"(r[0]), "=r"(r[1]), "=r"(r[2]), "=r"(r[3]) : "r"(a));
}
__device__ __forceinline__ void mma_bf16(float c[4], const uint32_t a[4], const uint32_t b[2]) {
    asm volatile("mma.sync.aligned.m16n8k16.row.col.f32.bf16.bf16.f32 "
                 "{%0,%1,%2,%3}, {%4,%5,%6,%7}, {%8,%9}, {%0,%1,%2,%3};"
                 : "+f"(c[0]), "+f"(c[1]), "+f"(c[2]), "+f"(c[3])
                 : "r"(a[0]), "r"(a[1]), "r"(a[2]), "r"(a[3]), "r"(b[0]), "r"(b[1]));
}

__device__ __forceinline__ float gelu_exact(float v) {
    return 0.5f * v * (1.0f + erff(v * 0.70710678118654752440f));
}

// cp.async (compiles on this toolchain; tcgen05 does NOT)
__device__ __forceinline__ void cp16(uint32_t dst, const void* src) {
    asm volatile("cp.async.cg.shared.global [%0], [%1], 16;" :: "r"(dst), "l"(src));
}
__device__ __forceinline__ void cp_commit() { asm volatile("cp.async.commit_group;"); }
__device__ __forceinline__ void cp_wait0()  { asm volatile("cp.async.wait_group 0;" ::: "memory"); }

// ---------------------------------------------------------------------------
// Merged weight split: all 6 weights in one launch (pointer-select by block).
// ---------------------------------------------------------------------------
__global__ void __launch_bounds__(256)
split6_kernel(const float* w0, __nv_bfloat16* h0, __nv_bfloat16* l0,
              const float* w1, __nv_bfloat16* h1, __nv_bfloat16* l1,
              const float* w2, __nv_bfloat16* h2, __nv_bfloat16* l2,
              const float* w3, __nv_bfloat16* h3, __nv_bfloat16* l3,
              const float* w4, __nv_bfloat16* h4, __nv_bfloat16* l4,
              const float* w5, __nv_bfloat16* h5, __nv_bfloat16* l5)
{
    const int b = blockIdx.x;
    const float* W; __nv_bfloat16 *H, *L; size_t off;
    if      (b < 1024) { W = w0; H = h0; L = l0; off = (size_t)b * 1024; }
    else if (b < 2048) { W = w1; H = h1; L = l1; off = (size_t)(b - 1024) * 1024; }
    else if (b < 3072) { W = w2; H = h2; L = l2; off = (size_t)(b - 2048) * 1024; }
    else if (b < 4096) { W = w3; H = h3; L = l3; off = (size_t)(b - 3072) * 1024; }
    else if (b < 8192) { W = w4; H = h4; L = l4; off = (size_t)(b - 4096) * 1024; }
    else               { W = w5; H = h5; L = l5; off = (size_t)(b - 8192) * 1024; }
    const size_t i = off + threadIdx.x * 4;
    float4 v = *(const float4*)(W + i);
    split_store4(v, H + i, L + i);
}

// ---------------------------------------------------------------------------
// LayerNorm: writes split bf16 (h, l)
// ---------------------------------------------------------------------------
__global__ void __launch_bounds__(256)
layernorm_kernel(const float* __restrict__ x, const float* __restrict__ w,
                 const float* __restrict__ bsh,
                 __nv_bfloat16* __restrict__ yh, __nv_bfloat16* __restrict__ yl)
{
    __shared__ float s1[256];
    __shared__ float s2[256];
    const int tid = threadIdx.x;
    const size_t row = blockIdx.x;
    const float4* xr = (const float4*)(x + row * Emb);
    float4 v = xr[tid];

    float a = v.x + v.y + v.z + v.w;
    float b = v.x * v.x + v.y * v.y + v.z * v.z + v.w * v.w;
    s1[tid] = a; s2[tid] = b;
    __syncthreads();
    #pragma unroll
    for (int st = 128; st > 0; st >>= 1) {
        if (tid < st) { s1[tid] += s1[tid + st]; s2[tid] += s2[tid + st]; }
        __syncthreads();
    }
    const float mu   = s1[0] * (1.0f / Emb);
    const float var  = s2[0] * (1.0f / Emb) - mu * mu;
    const float rstd = rsqrtf(var + 1e-5f);

    float4 wv = ((const float4*)w)[tid];
    float4 bv = ((const float4*)bsh)[tid];
    float4 o;
    o.x = (v.x - mu) * rstd * wv.x + bv.x;
    o.y = (v.y - mu) * rstd * wv.y + bv.y;
    o.z = (v.z - mu) * rstd * wv.z + bv.z;
    o.w = (v.w - mu) * rstd * wv.w + bv.w;
    split_store4(o, yh + row * Emb + tid * 4, yl + row * Emb + tid * 4);
}

// ---------------------------------------------------------------------------
// GEMM tiling constants (75776 B smem; launch_bounds targets 2 CTAs/SM)
// ---------------------------------------------------------------------------
#define BM 128
#define BN 128
#define BK 32
#define PA 40
#define PB 136
#define AT_ELE (BM * PA)                       // 5120 bf16 per A tile
#define BT_ELE (BK * PB)                       // 4352 bf16 per B tile
#define BUF_ELE (2 * AT_ELE + 2 * BT_ELE)      // 18944 bf16 per buffer
#define GEMM_SMEM (2 * BUF_ELE * 2)            // 75776 bytes

__device__ __forceinline__ void stage_tile(
    __nv_bfloat16* buf,
    const __nv_bfloat16* __restrict__ Ah_g, const __nv_bfloat16* __restrict__ Al_g,
    const __nv_bfloat16* __restrict__ Bh_g, const __nv_bfloat16* __restrict__ Bl_g,
    int bm, int bn, int k0, int N, int K, int tid)
{
    __nv_bfloat16* Ah = buf;
    __nv_bfloat16* Al = buf + AT_ELE;
    __nv_bfloat16* Bh = buf + 2 * AT_ELE;
    __nv_bfloat16* Bl = buf + 2 * AT_ELE + BT_ELE;
    #pragma unroll
    for (int i = 0; i < 2; i++) {
        const int u   = tid + 256 * i;
        const int row = u >> 2;
        const int kc  = (u & 3) * 8;
        const size_t go = (size_t)(bm + row) * K + k0 + kc;
        cp16(cvta_s(Ah + row * PA + kc), Ah_g + go);
        cp16(cvta_s(Al + row * PA + kc), Al_g + go);
    }
    #pragma unroll
    for (int i = 0; i < 2; i++) {
        const int u   = tid + 256 * i;
        const int row = u >> 4;
        const int nc  = (u & 15) * 8;
        const size_t go = (size_t)(k0 + row) * N + bn + nc;
        cp16(cvta_s(Bh + row * PB + nc), Bh_g + go);
        cp16(cvta_s(Bl + row * PB + nc), Bl_g + go);
    }
}

// Inner compute for one staged buffer (shared by both GEMM kernels).
__device__ __forceinline__ void gemm_tile_compute(
    const __nv_bfloat16* buf, float acc[4][4][4],
    int wm, int wn, int a_r, int a_kh, int b_c4)
{
    const __nv_bfloat16* Ahb = buf;
    const __nv_bfloat16* Alb = buf + AT_ELE;
    const __nv_bfloat16* Bhb = buf + 2 * AT_ELE;
    const __nv_bfloat16* Blb = buf + 2 * AT_ELE + BT_ELE;

    #pragma unroll
    for (int kk = 0; kk < BK; kk += 16) {
        uint32_t ah[4][4], al[4][4];
        #pragma unroll
        for (int mi = 0; mi < 4; mi++) {
            const int row = wm + mi * 16 + a_r;
            const int kc  = kk + a_kh;
            ldsm_x4(ah[mi], cvta_s(Ahb + row * PA + kc));
            ldsm_x4(al[mi], cvta_s(Alb + row * PA + kc));
        }
        #pragma unroll
        for (int ni2 = 0; ni2 < 2; ni2++) {
            const int n0 = wn + ni2 * 16;
            uint32_t bh4[4], bl4[4];
            const int boff = (kk + a_r) * PB + n0 + b_c4;
            ldsm_x4t(bh4, cvta_s(Bhb + boff));
            ldsm_x4t(bl4, cvta_s(Blb + boff));
            #pragma unroll
            for (int mi = 0; mi < 4; mi++) {
                mma_bf16(acc[mi][2 * ni2],     ah[mi], &bh4[0]);
                mma_bf16(acc[mi][2 * ni2],     al[mi], &bh4[0]);
                mma_bf16(acc[mi][2 * ni2],     ah[mi], &bl4[0]);
                mma_bf16(acc[mi][2 * ni2 + 1], ah[mi], &bh4[2]);
                mma_bf16(acc[mi][2 * ni2 + 1], al[mi], &bh4[2]);
                mma_bf16(acc[mi][2 * ni2 + 1], ah[mi], &bl4[2]);
            }
        }
    }
}

// ---------------------------------------------------------------------------
// Generic bf16-split GEMM, PERSISTENT tiles (1D grid, stride over tiles).
// EPI: 1 = bias+res fp32 out; 2 = bias+GELU split out.
// ---------------------------------------------------------------------------
template <int EPI>
__global__ void __launch_bounds__(256, 2)
mma_gemm_kernel(const __nv_bfloat16* __restrict__ Ah_g, const __nv_bfloat16* __restrict__ Al_g,
                const __nv_bfloat16* __restrict__ Bh_g, const __nv_bfloat16* __restrict__ Bl_g,
                const float* __restrict__ bias, const float* __restrict__ res,
                float* __restrict__ Cf,
                __nv_bfloat16* __restrict__ Ch, __nv_bfloat16* __restrict__ Cl,
                int nx, int ntiles, int N, int K)
{
    extern __shared__ __nv_bfloat16 smb[];

    const int tid  = threadIdx.x;
    const int lane = tid & 31;
    const int warp = tid >> 5;
    const int wm   = (warp >> 2) * 64;
    const int wn   = (warp & 3) * 32;
    const int g    = lane >> 2;
    const int tg   = lane & 3;

    const int a_r  = (lane & 7) + ((lane >> 3) & 1) * 8;
    const int a_kh = (lane >> 4) * 8;
    const int b_c4 = (lane >> 4) * 8;
    const int nk   = K >> 5;

    for (int tile = blockIdx.x; tile < ntiles; tile += gridDim.x) {
        const int bm = (tile / nx) * BM;
        const int bn = (tile % nx) * BN;

        float acc[4][4][4];
        #pragma unroll
        for (int mi = 0; mi < 4; mi++)
            #pragma unroll
            for (int ni = 0; ni < 4; ni++)
                #pragma unroll
                for (int c = 0; c < 4; c++) acc[mi][ni][c] = 0.0f;

        stage_tile(smb, Ah_g, Al_g, Bh_g, Bl_g, bm, bn, 0, N, K, tid);
        cp_commit();

        for (int t = 0; t < nk; t++) {
            cp_wait0();
            __syncthreads();
            if (t + 1 < nk) {
                stage_tile(smb + ((t + 1) & 1) * BUF_ELE, Ah_g, Al_g, Bh_g, Bl_g,
                           bm, bn, (t + 1) << 5, N, K, tid);
                cp_commit();
            }
            gemm_tile_compute(smb + (t & 1) * BUF_ELE, acc, wm, wn, a_r, a_kh, b_c4);
        }

        #pragma unroll
        for (int mi = 0; mi < 4; mi++) {
            #pragma unroll
            for (int ni = 0; ni < 4; ni++) {
                const int col = bn + wn + ni * 8 + tg * 2;
                const float bx = bias[col], by = bias[col + 1];
                #pragma unroll
                for (int half = 0; half < 2; half++) {
                    const size_t row = (size_t)(bm + wm + mi * 16 + g + half * 8);
                    float vx = acc[mi][ni][half * 2 + 0] + bx;
                    float vy = acc[mi][ni][half * 2 + 1] + by;
                    if (EPI == 1) {
                        float2 rv = *(const float2*)&res[row * N + col];
                        vx += rv.x; vy += rv.y;
                    }
                    if (EPI == 2) {
                        vx = gelu_exact(vx); vy = gelu_exact(vy);
                        uint32_t h, l;
                        splitpack(vx, vy, h, l);
                        *(uint32_t*)&Ch[row * N + col] = h;
                        *(uint32_t*)&Cl[row * N + col] = l;
                    } else {
                        *(float2*)&Cf[row * N + col] = make_float2(vx, vy);
                    }
                }
            }
        }
    }
}

// ---------------------------------------------------------------------------
// Fused QKV GEMM, PERSISTENT tiles: 768 tiles (24 x 32); slab-selects wq/wk/wv.
// Output: interleaved [ROWS, 3072] split bf16.
// ---------------------------------------------------------------------------
__global__ void __launch_bounds__(256, 2)
qkv_gemm_kernel(const __nv_bfloat16* __restrict__ Ah_g, const __nv_bfloat16* __restrict__ Al_g,
                const __nv_bfloat16* __restrict__ w0h, const __nv_bfloat16* __restrict__ w0l,
                const __nv_bfloat16* __restrict__ w1h, const __nv_bfloat16* __restrict__ w1l,
                const __nv_bfloat16* __restrict__ w2h, const __nv_bfloat16* __restrict__ w2l,
                const float* __restrict__ b0, const float* __restrict__ b1,
                const float* __restrict__ b2,
                __nv_bfloat16* __restrict__ Ch, __nv_bfloat16* __restrict__ Cl)
{
    extern __shared__ __nv_bfloat16 smb[];

    const int tid  = threadIdx.x;
    const int lane = tid & 31;
    const int warp = tid >> 5;
    const int wm   = (warp >> 2) * 64;
    const int wn   = (warp & 3) * 32;
    const int g    = lane >> 2;
    const int tg   = lane & 3;

    const int a_r  = (lane & 7) + ((lane >> 3) & 1) * 8;
    const int a_kh = (lane >> 4) * 8;
    const int b_c4 = (lane >> 4) * 8;
    const int nk   = Emb >> 5;   // 32

    for (int tile = blockIdx.x; tile < 24 * 32; tile += gridDim.x) {
        const int bx = tile % 24;
        const int bm = (tile / 24) * BM;
        const int which = bx >> 3;
        const __nv_bfloat16* Bh_g = (which == 0) ? w0h : (which == 1) ? w1h : w2h;
        const __nv_bfloat16* Bl_g = (which == 0) ? w0l : (which == 1) ? w1l : w2l;
        const float* bias         = (which == 0) ? b0  : (which == 1) ? b1  : b2;
        const int bnL = (bx & 7) * BN;   // within this weight's N=1024
        const int bnO = bx * BN;         // within 3072 output

        float acc[4][4][4];
        #pragma unroll
        for (int mi = 0; mi < 4; mi++)
            #pragma unroll
            for (int ni = 0; ni < 4; ni++)
                #pragma unroll
                for (int c = 0; c < 4; c++) acc[mi][ni][c] = 0.0f;

        stage_tile(smb, Ah_g, Al_g, Bh_g, Bl_g, bm, bnL, 0, Emb, Emb, tid);
        cp_commit();

        for (int t = 0; t < nk; t++) {
            cp_wait0();
            __syncthreads();
            if (t + 1 < nk) {
                stage_tile(smb + ((t + 1) & 1) * BUF_ELE, Ah_g, Al_g, Bh_g, Bl_g,
                           bm, bnL, (t + 1) << 5, Emb, Emb, tid);
                cp_commit();
            }
            gemm_tile_compute(smb + (t & 1) * BUF_ELE, acc, wm, wn, a_r, a_kh, b_c4);
        }

        // epilogue: bias + splitpack into [ROWS, 3072]
        #pragma unroll
        for (int mi = 0; mi < 4; mi++) {
            #pragma unroll
            for (int ni = 0; ni < 4; ni++) {
                const int colL = bnL + wn + ni * 8 + tg * 2;
                const int colO = bnO + wn + ni * 8 + tg * 2;
                const float bx2 = bias[colL], by2 = bias[colL + 1];
                #pragma unroll
                for (int half = 0; half < 2; half++) {
                    const size_t row = (size_t)(bm + wm + mi * 16 + g + half * 8);
                    float vx = acc[mi][ni][half * 2 + 0] + bx2;
                    float vy = acc[mi][ni][half * 2 + 1] + by2;
                    uint32_t h, l;
                    splitpack(vx, vy, h, l);
                    *(uint32_t*)&Ch[row * QKVS + colO] = h;
                    *(uint32_t*)&Cl[row * QKVS + colO] = l;
                }
            }
        }
    }
}

// ---------------------------------------------------------------------------
// Tensor-core flash attention over the fused qkv buffer.
// Q staged into buffer 0, fragments hoisted, buffer 0 recycled for KV.
// Softmax in exp2 domain with running max kept PRE-SCALED:
//   p = ex2(fma(s, C, -m_s)) ; alpha = ex2(m_s_old - m_s_new)
// ---------------------------------------------------------------------------
#define PQ 72
#define KV_ELE   (64 * PQ)             // 4608 ele per array
#define KVBUF_ELE (4 * KV_ELE)         // 18432 ele per buffer (36864 B)
#define ATTN_SMEM (2 * KVBUF_ELE * 2)  // 73728 bytes

__device__ __forceinline__ void stage_kv(
    __nv_bfloat16* buf,
    const __nv_bfloat16* __restrict__ qkvh, const __nv_bfloat16* __restrict__ qkvl,
    size_t kbase, size_t vbase, int c0, int tid)
{
    #pragma unroll
    for (int i = 0; i < 2; i++) {
        const int u = tid + 256 * i;
        const int r = u >> 3;
        const int c = (u & 7) * 8;
        const size_t gk = kbase + (size_t)(c0 + r) * QKVS + c;
        const size_t gv = vbase + (size_t)(c0 + r) * QKVS + c;
        const int so = r * PQ + c;
        cp16(cvta_s(buf + 0 * KV_ELE + so), qkvh + gk);
        cp16(cvta_s(buf + 1 * KV_ELE + so), qkvl + gk);
        cp16(cvta_s(buf + 2 * KV_ELE + so), qkvh + gv);
        cp16(cvta_s(buf + 3 * KV_ELE + so), qkvl + gv);
    }
}

__global__ void __launch_bounds__(256, 2)
flash_attn_kernel(const __nv_bfloat16* __restrict__ qkvh, const __nv_bfloat16* __restrict__ qkvl,
                  __nv_bfloat16* __restrict__ Oh, __nv_bfloat16* __restrict__ Ol)
{
    extern __shared__ __nv_bfloat16 sb[];   // [2][KVBUF_ELE]

    const int tid  = threadIdx.x;
    const int lane = tid & 31;
    const int warp = tid >> 5;
    const int g    = lane >> 2;
    const int tg   = lane & 3;
    const int l7   = lane & 7;
    const int b8   = (lane >> 3) & 1;
    const int b16  = lane >> 4;

    const int bh = blockIdx.y;
    const int b = bh >> 4, h = bh & 15;
    const int q0 = blockIdx.x << 7;
    const size_t bb    = (size_t)b * Lseq * QKVS;
    const size_t qbase = bb + (size_t)h * DHd;
    const size_t kbase = qbase + Emb;
    const size_t vbase = qbase + 2 * Emb;

    // ---- stage Q into buffer 0 ----
    {
        __nv_bfloat16* Qh = sb;
        __nv_bfloat16* Ql = sb + 128 * PQ;
        #pragma unroll
        for (int i = 0; i < 4; i++) {
            const int u = tid + 256 * i;
            const int r = u >> 3;
            const int c = (u & 7) * 8;
            const size_t go = qbase + (size_t)(q0 + r) * QKVS + c;
            cp16(cvta_s(Qh + r * PQ + c), qkvh + go);
            cp16(cvta_s(Ql + r * PQ + c), qkvl + go);
        }
    }
    cp_commit();
    cp_wait0();
    __syncthreads();

    // ---- Q fragments -> registers ----
    const int a_r  = l7 + b8 * 8;
    const int a_kh = b16 * 8;
    uint32_t qfh[4][4], qfl[4][4];
    {
        const __nv_bfloat16* Qh = sb;
        const __nv_bfloat16* Ql = sb + 128 * PQ;
        const int row = warp * 16 + a_r;
        #pragma unroll
        for (int ks = 0; ks < 4; ks++) {
            const int kc = 16 * ks + a_kh;
            ldsm_x4(qfh[ks], cvta_s(Qh + row * PQ + kc));
            ldsm_x4(qfl[ks], cvta_s(Ql + row * PQ + kc));
        }
    }
    __syncthreads();   // buffer 0 is now free

    // ---- KV tile 0 -> buffer 1 ----
    stage_kv(sb + KVBUF_ELE, qkvh, qkvl, kbase, vbase, 0, tid);
    cp_commit();

    float oacc[8][4];
    #pragma unroll
    for (int nj = 0; nj < 8; nj++)
        #pragma unroll
        for (int c = 0; c < 4; c++) oacc[nj][c] = 0.0f;
    // running max kept in the SCALED (exp2) domain
    float mAs = -1e30f, mBs = -1e30f, lA = 0.0f, lB = 0.0f;

    const int nkb = Lseq / 64;
    for (int kb = 0; kb < nkb; kb++) {
        cp_wait0();
        __syncthreads();
        if (kb + 1 < nkb) {
            stage_kv(sb + (kb & 1) * KVBUF_ELE, qkvh, qkvl, kbase, vbase,
                     (kb + 1) << 6, tid);
            cp_commit();
        }

        const __nv_bfloat16* cur = sb + ((kb + 1) & 1) * KVBUF_ELE;
        const __nv_bfloat16* Kh = cur;
        const __nv_bfloat16* Kl = cur + KV_ELE;
        const __nv_bfloat16* Vh = cur + 2 * KV_ELE;
        const __nv_bfloat16* Vl = cur + 3 * KV_ELE;

        // ---- S = Q K^T (raw; scale folded into the exp2 fma below) ----
        float sacc[8][4];
        #pragma unroll
        for (int ni = 0; ni < 8; ni++)
            #pragma unroll
            for (int c = 0; c < 4; c++) sacc[ni][c] = 0.0f;

        #pragma unroll
        for (int ks = 0; ks < 4; ks++) {
            #pragma unroll
            for (int ni2 = 0; ni2 < 4; ni2++) {
                const int n0 = ni2 * 16;
                uint32_t kh4[4], kl4[4];
                const int koff = (n0 + l7 + b16 * 8) * PQ + 16 * ks + b8 * 8;
                ldsm_x4(kh4, cvta_s(Kh + koff));
                ldsm_x4(kl4, cvta_s(Kl + koff));
                mma_bf16(sacc[2 * ni2],     qfh[ks], &kh4[0]);
                mma_bf16(sacc[2 * ni2],     qfl[ks], &kh4[0]);
                mma_bf16(sacc[2 * ni2],     qfh[ks], &kl4[0]);
                mma_bf16(sacc[2 * ni2 + 1], qfh[ks], &kh4[2]);
                mma_bf16(sacc[2 * ni2 + 1], qfl[ks], &kh4[2]);
                mma_bf16(sacc[2 * ni2 + 1], qfh[ks], &kl4[2]);
            }
        }

        // ---- online softmax: raw max, scaled-domain tracking ----
        float tA = -1e30f, tB = -1e30f;
        #pragma unroll
        for (int ni = 0; ni < 8; ni++) {
            tA = fmaxf(tA, fmaxf(sacc[ni][0], sacc[ni][1]));
            tB = fmaxf(tB, fmaxf(sacc[ni][2], sacc[ni][3]));
        }
        tA = fmaxf(tA, __shfl_xor_sync(0xffffffffu, tA, 1));
        tA = fmaxf(tA, __shfl_xor_sync(0xffffffffu, tA, 2));
        tB = fmaxf(tB, __shfl_xor_sync(0xffffffffu, tB, 1));
        tB = fmaxf(tB, __shfl_xor_sync(0xffffffffu, tB, 2));

        const float mAns = fmaxf(mAs, tA * SCALE_LOG2E);
        const float mBns = fmaxf(mBs, tB * SCALE_LOG2E);
        const float aA = ex2(mAs - mAns), aB = ex2(mBs - mBns);
        mAs = mAns; mBs = mBns;

        float sA = 0.0f, sB = 0.0f;
        #pragma unroll
        for (int ni = 0; ni < 8; ni++) {
            float p0 = ex2(fmaf(sacc[ni][0], SCALE_LOG2E, -mAns));
            float p1 = ex2(fmaf(sacc[ni][1], SCALE_LOG2E, -mAns));
            float p2 = ex2(fmaf(sacc[ni][2], SCALE_LOG2E, -mBns));
            float p3 = ex2(fmaf(sacc[ni][3], SCALE_LOG2E, -mBns));
            sacc[ni][0] = p0; sacc[ni][1] = p1;
            sacc[ni][2] = p2; sacc[ni][3] = p3;
            sA += p0 + p1; sB += p2 + p3;
        }
        sA += __shfl_xor_sync(0xffffffffu, sA, 1);
        sA += __shfl_xor_sync(0xffffffffu, sA, 2);
        sB += __shfl_xor_sync(0xffffffffu, sB, 1);
        sB += __shfl_xor_sync(0xffffffffu, sB, 2);
        lA = lA * aA + sA;
        lB = lB * aB + sB;

        #pragma unroll
        for (int nj = 0; nj < 8; nj++) {
            oacc[nj][0] *= aA; oacc[nj][1] *= aA;
            oacc[nj][2] *= aB; oacc[nj][3] *= aB;
        }

        // ---- O += P V (V b-frags via x4t: two n-groups per ld) ----
        #pragma unroll
        for (int ks = 0; ks < 4; ks++) {
            uint32_t pfh[4], pfl[4];
            splitpack(sacc[2 * ks][0],     sacc[2 * ks][1],     pfh[0], pfl[0]);
            splitpack(sacc[2 * ks][2],     sacc[2 * ks][3],     pfh[1], pfl[1]);
            splitpack(sacc[2 * ks + 1][0], sacc[2 * ks + 1][1], pfh[2], pfl[2]);
            splitpack(sacc[2 * ks + 1][2], sacc[2 * ks + 1][3], pfh[3], pfl[3]);
            #pragma unroll
            for (int nj2 = 0; nj2 < 4; nj2++) {
                const int n0 = nj2 * 16;
                uint32_t vh4[4], vl4[4];
                const int voff = (16 * ks + a_r) * PQ + n0 + b16 * 8;
                ldsm_x4t(vh4, cvta_s(Vh + voff));
                ldsm_x4t(vl4, cvta_s(Vl + voff));
                mma_bf16(oacc[2 * nj2],     pfh, &vh4[0]);
                mma_bf16(oacc[2 * nj2],     pfl, &vh4[0]);
                mma_bf16(oacc[2 * nj2],     pfh, &vl4[0]);
                mma_bf16(oacc[2 * nj2 + 1], pfh, &vh4[2]);
                mma_bf16(oacc[2 * nj2 + 1], pfl, &vh4[2]);
                mma_bf16(oacc[2 * nj2 + 1], pfh, &vl4[2]);
            }
        }
    }

    // ---- finalize: ctx = O / l, written as split bf16 (stride Emb) ----
    const float iA = 1.0f / lA, iB = 1.0f / lB;
    const size_t obase = (size_t)b * Lseq * Emb + (size_t)h * DHd;
    const int rowA = q0 + warp * 16 + g;
    #pragma unroll
    for (int nj = 0; nj < 8; nj++) {
        const int d = nj * 8 + tg * 2;
        uint32_t hA, lAa, hB, lBb;
        splitpack(oacc[nj][0] * iA, oacc[nj][1] * iA, hA, lAa);
        splitpack(oacc[nj][2] * iB, oacc[nj][3] * iB, hB, lBb);
        const size_t offA = obase + (size_t)rowA * Emb + d;
        const size_t offB = obase + (size_t)(rowA + 8) * Emb + d;
        *(uint32_t*)&Oh[offA] = hA;  *(uint32_t*)&Ol[offA] = lAa;
        *(uint32_t*)&Oh[offB] = hB;  *(uint32_t*)&Ol[offB] = lBb;
    }
}

// ---------------------------------------------------------------------------
// Launch
// ---------------------------------------------------------------------------
extern "C" void kernel_launch(void* const* d_in, const int* in_sizes, int n_in,
                              void* d_out, int out_size)
{
    const float* x     = (const float*)d_in[0];
    const float* ln1_w = (const float*)d_in[1];
    const float* ln1_b = (const float*)d_in[2];
    const float* wq    = (const float*)d_in[3];
    const float* bq    = (const float*)d_in[4];
    const float* wk    = (const float*)d_in[5];
    const float* bk    = (const float*)d_in[6];
    const float* wv    = (const float*)d_in[7];
    const float* bv    = (const float*)d_in[8];
    const float* wo    = (const float*)d_in[9];
    const float* bo    = (const float*)d_in[10];
    const float* ln2_w = (const float*)d_in[11];
    const float* ln2_b = (const float*)d_in[12];
    const float* wu    = (const float*)d_in[13];
    const float* bu    = (const float*)d_in[14];
    const float* wd    = (const float*)d_in[15];
    const float* bd    = (const float*)d_in[16];
    float* out = (float*)d_out;

    __nv_bfloat16 *xnh, *xnl, *hnh, *hnl, *ctxh, *ctxl, *uph, *upl, *qkvh, *qkvl;
    __nv_bfloat16 *wqh, *wql, *wkh, *wkl, *wvh, *wvl, *woh, *wol, *wuh, *wul, *wdh, *wdl;
    float *hidden;
    cudaGetSymbolAddress((void**)&xnh,  g_xn_h);  cudaGetSymbolAddress((void**)&xnl,  g_xn_l);
    cudaGetSymbolAddress((void**)&hnh,  g_hn_h);  cudaGetSymbolAddress((void**)&hnl,  g_hn_l);
    cudaGetSymbolAddress((void**)&ctxh, g_ctx_h); cudaGetSymbolAddress((void**)&ctxl, g_ctx_l);
    cudaGetSymbolAddress((void**)&uph,  g_up_h);  cudaGetSymbolAddress((void**)&upl,  g_up_l);
    cudaGetSymbolAddress((void**)&qkvh, g_qkv_h); cudaGetSymbolAddress((void**)&qkvl, g_qkv_l);
    cudaGetSymbolAddress((void**)&hidden, g_hidden);
    cudaGetSymbolAddress((void**)&wqh, g_wq_h);   cudaGetSymbolAddress((void**)&wql, g_wq_l);
    cudaGetSymbolAddress((void**)&wkh, g_wk_h);   cudaGetSymbolAddress((void**)&wkl, g_wk_l);
    cudaGetSymbolAddress((void**)&wvh, g_wv_h);   cudaGetSymbolAddress((void**)&wvl, g_wv_l);
    cudaGetSymbolAddress((void**)&woh, g_wo_h);   cudaGetSymbolAddress((void**)&wol, g_wo_l);
    cudaGetSymbolAddress((void**)&wuh, g_wu_h);   cudaGetSymbolAddress((void**)&wul, g_wu_l);
    cudaGetSymbolAddress((void**)&wdh, g_wd_h);   cudaGetSymbolAddress((void**)&wdl, g_wd_l);

    cudaFuncSetAttribute(mma_gemm_kernel<1>, cudaFuncAttributeMaxDynamicSharedMemorySize, GEMM_SMEM);
    cudaFuncSetAttribute(mma_gemm_kernel<2>, cudaFuncAttributeMaxDynamicSharedMemorySize, GEMM_SMEM);
    cudaFuncSetAttribute(qkv_gemm_kernel,    cudaFuncAttributeMaxDynamicSharedMemorySize, GEMM_SMEM);
    cudaFuncSetAttribute(flash_attn_kernel,  cudaFuncAttributeMaxDynamicSharedMemorySize, ATTN_SMEM);

    // persistent-grid slot count: 2 CTAs per SM
    int smCount = 148;
    cudaDeviceGetAttribute(&smCount, cudaDevAttrMultiProcessorCount, 0);
    const int nslots = 2 * smCount;
    const int gQKV = (768  < nslots) ? 768  : nslots;
    const int gUP  = (1024 < nslots) ? 1024 : nslots;
    const int gE   = (256  < nslots) ? 256  : nslots;

    // 0) split all weights in one launch
    split6_kernel<<<12288, 256>>>(wq, wqh, wql, wk, wkh, wkl, wv, wvh, wvl,
                                  wo, woh, wol, wu, wuh, wul, wd, wdh, wdl);

    // 1) LN1 -> split xn
    layernorm_kernel<<<ROWS, 256>>>(x, ln1_w, ln1_b, xnh, xnl);
    // 2) fused QKV projection -> split [ROWS, 3072] (persistent, 768 tiles)
    qkv_gemm_kernel<<<gQKV, 256, GEMM_SMEM>>>(xnh, xnl,
                                              wqh, wql, wkh, wkl, wvh, wvl,
                                              bq, bk, bv, qkvh, qkvl);
    // 3) Flash attention -> split ctx
    flash_attn_kernel<<<dim3(Lseq / 128, Bb * NH), 256, ATTN_SMEM>>>(qkvh, qkvl, ctxh, ctxl);
    // 4) O projection + residual -> hidden (fp32)  [256 tiles]
    mma_gemm_kernel<1><<<gE, 256, GEMM_SMEM>>>(ctxh, ctxl, woh, wol, bo, x, hidden,
                                               nullptr, nullptr, 8, 256, Emb, Emb);
    // 5) LN2 -> split hn
    layernorm_kernel<<<ROWS, 256>>>(hidden, ln2_w, ln2_b, hnh, hnl);
    // 6) FFN up + GELU -> split up  [1024 tiles, persistent]
    mma_gemm_kernel<2><<<gUP, 256, GEMM_SMEM>>>(hnh, hnl, wuh, wul, bu, nullptr, nullptr,
                                                uph, upl, 32, 1024, FFd, Emb);
    // 7) FFN down + bias + residual -> out (fp32)  [256 tiles]
    mma_gemm_kernel<1><<<gE, 256, GEMM_SMEM>>>(uph, upl, wdh, wdl, bd, hidden, out,
                                               nullptr, nullptr, 8, 256, Emb, FFd);
}